// round 16
// baseline (speedup 1.0000x reference)
#include <cuda_runtime.h>
#include <math.h>
#include <stdint.h>

// Problem constants
#define CN 50000
#define CE 800000
#define CR 3
#define CT 16

typedef unsigned long long ull;

__device__ __forceinline__ ull pack2(float lo, float hi) {
    ull r; asm("mov.b64 %0, {%1,%2};" : "=l"(r) : "f"(lo), "f"(hi)); return r;
}
__device__ __forceinline__ ull fma2(ull a, ull b, ull c) {
    ull d; asm("fma.rn.f32x2 %0, %1, %2, %3;" : "=l"(d) : "l"(a), "l"(b), "l"(c)); return d;
}
__device__ __forceinline__ void unpack2(ull v, float& lo, float& hi) {
    asm("mov.b64 {%0,%1}, %2;" : "=f"(lo), "=f"(hi) : "l"(v));
}

// ---------------- scratch layout (floats) ----------------
constexpr size_t SZ_WCAT = 256 * 128;
constexpr size_t OFF_WCV = 0;
constexpr size_t OFF_WCS = OFF_WCV + SZ_WCAT;
constexpr size_t OFF_BCV = OFF_WCS + SZ_WCAT;
constexpr size_t OFF_BCS = OFF_BCV + 256;
constexpr size_t OFF_W3P = OFF_BCS + 256;                 // 128*256 (lin3, k-perm)
constexpr size_t OFF_W4P = OFF_W3P + 128 * 256;           // 128*384 (lin4, xp-combined)
constexpr size_t OFF_HV0 = OFF_W4P + 128 * 384;           // N*64 each
constexpr size_t OFF_HV1 = OFF_HV0 + (size_t)CN * 64;
constexpr size_t OFF_HS0 = OFF_HV1 + (size_t)CN * 64;
constexpr size_t OFF_HS1 = OFF_HS0 + (size_t)CN * 64;
constexpr size_t OFF_CV  = OFF_HS1 + (size_t)CN * 64;
constexpr size_t OFF_CS  = OFF_CV + (size_t)CN * 64;
constexpr size_t OFF_XCAT= OFF_CS + (size_t)CN * 64;      // [xv|xp|xs] N*384
constexpr size_t OFF_BIG = OFF_XCAT + (size_t)CN * 384;   // [unused(384) | xin0..2] N*768
constexpr size_t OFF_P1  = OFF_BIG + (size_t)CN * 768;    // 3 x N*128
constexpr size_t OFF_P2  = OFF_P1 + (size_t)3 * CN * 128; // 3 x N*128
constexpr size_t OFF_Y   = OFF_P2 + (size_t)3 * CN * 128; // 3 x 3 x N*128
constexpr size_t OFF_RES = OFF_Y + (size_t)9 * CN * 128;  // 3 x N*128
constexpr size_t OFF_DEG = OFF_RES + (size_t)3 * CN * 128;// 3 x N
constexpr size_t OFF_DINV= OFF_DEG + (size_t)3 * CN;      // 3 x N
constexpr size_t OFF_OUTP= OFF_DINV + (size_t)3 * CN;     // 6 x N x 2 partials
constexpr size_t SCRATCH_TOTAL = OFF_OUTP + (size_t)6 * CN * 2 + 64;

__device__ float g_scratch[SCRATCH_TOTAL];
__device__ int g_csr[3 * CE];
__device__ int g_off[3 * (CN + 1)];
__device__ int g_cur[3 * CN];

// THETAS coefficients on (p0, p1, p2)
__device__ __constant__ float c_th0[5] = {0.8f, 3.0f, 0.0f, 0.0f, -0.2f};
__device__ __constant__ float c_th1[5] = {-0.5f, -3.0f, 3.0f, 0.0f, 0.5f};
__device__ __constant__ float c_th2[5] = {0.0f, 0.75f, -1.5f, 0.75f, 0.0f};

// =====================================================================
// FFMA2 GEMM core (PROVEN shape)
// =====================================================================
#define TILE_COMPUTE(cur)                                                      \
    _Pragma("unroll")                                                          \
    for (int kk = 0; kk < 16; kk++) {                                          \
        float a[8]; ull b2[4];                                                 \
        *(float4*)(&a[0]) = *(const float4*)(&As[cur][kk][ty * 8]);            \
        *(float4*)(&a[4]) = *(const float4*)(&As[cur][kk][ty * 8 + 4]);        \
        {                                                                      \
            const ulonglong2* wp = (const ulonglong2*)(&Ws[cur][kk][tx * 8]);  \
            ulonglong2 w0 = wp[0]; ulonglong2 w1 = wp[1];                      \
            b2[0] = w0.x; b2[1] = w0.y; b2[2] = w1.x; b2[3] = w1.y;            \
        }                                                                      \
        _Pragma("unroll")                                                      \
        for (int i = 0; i < 8; i++) {                                          \
            ull ai = pack2(a[i], a[i]);                                        \
            _Pragma("unroll")                                                  \
            for (int jj = 0; jj < 4; jj++)                                     \
                acc2[i][jj] = fma2(ai, b2[jj], acc2[i][jj]);                   \
        }                                                                      \
    }

#define STORE_TILE(buf)                                                                         \
    As[buf][lk+0][lr] = pa0.x; As[buf][lk+1][lr] = pa0.y;                                       \
    As[buf][lk+2][lr] = pa0.z; As[buf][lk+3][lr] = pa0.w;                                       \
    As[buf][lk+0][lr+64] = pa1.x; As[buf][lk+1][lr+64] = pa1.y;                                 \
    As[buf][lk+2][lr+64] = pa1.z; As[buf][lk+3][lr+64] = pa1.w;                                 \
    Ws[buf][lk+0][lr] = pw0.x; Ws[buf][lk+1][lr] = pw0.y;                                       \
    Ws[buf][lk+2][lr] = pw0.z; Ws[buf][lk+3][lr] = pw0.w;                                       \
    Ws[buf][lk+0][lr+64] = pw1.x; Ws[buf][lk+1][lr+64] = pw1.y;                                 \
    Ws[buf][lk+2][lr+64] = pw1.z; Ws[buf][lk+3][lr+64] = pw1.w;

// gather one node's propagation (warp-wide), ldin-strided input
__device__ __forceinline__ void prop_node(
    int n, int col, const float* __restrict__ pinr, int ldin,
    const int* __restrict__ csr, const int* __restrict__ off,
    const float* __restrict__ dinv, float* __restrict__ outp)
{
    float4 acc = make_float4(0.f, 0.f, 0.f, 0.f);
    const int s0 = off[n], s1 = off[n + 1];
    int e = s0;
    for (; e + 4 <= s1; e += 4) {
        int sn0 = csr[e], sn1 = csr[e + 1], sn2 = csr[e + 2], sn3 = csr[e + 3];
        float d0 = __ldg(&dinv[sn0]), d1 = __ldg(&dinv[sn1]);
        float d2 = __ldg(&dinv[sn2]), d3 = __ldg(&dinv[sn3]);
        float4 v0 = *(const float4*)(pinr + (size_t)sn0 * ldin + col);
        float4 v1 = *(const float4*)(pinr + (size_t)sn1 * ldin + col);
        float4 v2 = *(const float4*)(pinr + (size_t)sn2 * ldin + col);
        float4 v3 = *(const float4*)(pinr + (size_t)sn3 * ldin + col);
        acc.x += v0.x * d0 + v1.x * d1 + v2.x * d2 + v3.x * d3;
        acc.y += v0.y * d0 + v1.y * d1 + v2.y * d2 + v3.y * d3;
        acc.z += v0.z * d0 + v1.z * d1 + v2.z * d2 + v3.z * d3;
        acc.w += v0.w * d0 + v1.w * d1 + v2.w * d2 + v3.w * d3;
    }
    for (; e < s1; e++) {
        int sn = csr[e];
        float ds = __ldg(&dinv[sn]);
        float4 v = *(const float4*)(pinr + (size_t)sn * ldin + col);
        acc.x += v.x * ds; acc.y += v.y * ds; acc.z += v.z * ds; acc.w += v.w * ds;
    }
    const float dn = dinv[n];
    float4 pv = *(const float4*)(pinr + (size_t)n * ldin + col);
    float4 o = make_float4(pv.x - acc.x * dn, pv.y - acc.y * dn,
                           pv.z - acc.z * dn, pv.w - acc.w * dn);
    *(float4*)(outp + (size_t)n * 128 + col) = o;
}

// ---------------- batched projection A ---------------------------------------
__global__ __launch_bounds__(256) void projA_kernel(
    const float* __restrict__ HV, const float* __restrict__ HS,
    const float* __restrict__ PERS,
    const float* __restrict__ Wl, const float* __restrict__ bl,
    const float* __restrict__ Wl1, const float* __restrict__ bl1,
    const float* __restrict__ Wp, const float* __restrict__ bp,
    float* __restrict__ XCAT)
{
    __shared__ float As[2][16][128];
    __shared__ float Ws[2][16][128];

    const int sel = blockIdx.x;
    const float* A = sel == 0 ? HV : (sel == 1 ? PERS : HS);
    const int lda = sel == 1 ? 32 : 64;
    const int K = lda;
    const float* W = sel == 0 ? Wl : (sel == 1 ? Wp : Wl1);
    const float* bias = sel == 0 ? bl : (sel == 1 ? bp : bl1);
    float* C = XCAT + 128 * sel;

    const int M = CN;
    const int bm = blockIdx.y * 128;
    const int tid = threadIdx.x;
    const int lr = tid >> 2;
    const int lk = (tid & 3) << 2;
    const int ty = tid >> 4, tx = tid & 15;

    ull acc2[8][4];
#pragma unroll
    for (int i = 0; i < 8; i++)
#pragma unroll
        for (int jj = 0; jj < 4; jj++) acc2[i][jj] = 0ull;

    int r0 = bm + lr;      r0 = r0 < M ? r0 : (M - 1);
    int r1 = bm + lr + 64; r1 = r1 < M ? r1 : (M - 1);

    float4 pa0, pa1, pw0, pw1;
    {
        int kg = lk;
        pa0 = *(const float4*)(A + (size_t)r0 * lda + kg);
        pa1 = *(const float4*)(A + (size_t)r1 * lda + kg);
        pw0 = *(const float4*)(W + (size_t)lr * K + kg);
        pw1 = *(const float4*)(W + (size_t)(lr + 64) * K + kg);
    }
    STORE_TILE(0)
    __syncthreads();

    const int ntiles = K >> 4;
    for (int t = 0; t < ntiles; t++) {
        const int cur = t & 1, nxt = cur ^ 1;
        const bool has = (t + 1) < ntiles;
        if (has) {
            int kg = ((t + 1) << 4) + lk;
            pa0 = *(const float4*)(A + (size_t)r0 * lda + kg);
            pa1 = *(const float4*)(A + (size_t)r1 * lda + kg);
            pw0 = *(const float4*)(W + (size_t)lr * K + kg);
            pw1 = *(const float4*)(W + (size_t)(lr + 64) * K + kg);
        }
        TILE_COMPUTE(cur)
        if (has) { STORE_TILE(nxt) }
        __syncthreads();
    }

    float bs0[8];
    *(float4*)(&bs0[0]) = *(const float4*)(bias + tx * 8);
    *(float4*)(&bs0[4]) = *(const float4*)(bias + tx * 8 + 4);

#pragma unroll
    for (int i = 0; i < 8; i++) {
        int m = bm + ty * 8 + i;
        if (m >= M) continue;
        float v[8];
#pragma unroll
        for (int jj = 0; jj < 4; jj++) {
            float lo, hi; unpack2(acc2[i][jj], lo, hi);
            v[2 * jj] = lo; v[2 * jj + 1] = hi;
        }
#pragma unroll
        for (int j = 0; j < 8; j++) {
            float x = v[j] + bs0[j];
            v[j] = x > 0.f ? x : 0.01f * x;
        }
        float* cp = C + (size_t)m * 384 + tx * 8;
        *(float4*)(cp)     = *(float4*)(&v[0]);
        *(float4*)(cp + 4) = *(float4*)(&v[4]);
    }
}

// ---------------- batched projection B + out partials -------------------------
__global__ __launch_bounds__(256) void projB_kernel(
    const float* __restrict__ XCAT,
    const float* __restrict__ Wl2, const float* __restrict__ bl2,
    const float* __restrict__ W3P, const float* __restrict__ bl3,
    const float* __restrict__ W4P, const float* __restrict__ bl4,
    const float* __restrict__ W6,
    float* __restrict__ BIG, float* __restrict__ OUTP)
{
    __shared__ float As[2][16][128];
    __shared__ float Ws[2][16][128];

    const int sel = blockIdx.x;
    const float* A = XCAT + (sel == 1 ? 128 : 0);
    const int K = sel == 2 ? 384 : 256;
    const float* W = sel == 0 ? Wl2 : (sel == 1 ? W3P : W4P);
    const float* bias = sel == 0 ? bl2 : (sel == 1 ? bl3 : bl4);
    float* C = BIG + 384 + 128 * sel;
    float* outp = OUTP + (size_t)sel * CN * 2;

    const int M = CN;
    const int bm = blockIdx.y * 128;
    const int tid = threadIdx.x;
    const int lr = tid >> 2;
    const int lk = (tid & 3) << 2;
    const int ty = tid >> 4, tx = tid & 15;

    ull acc2[8][4];
#pragma unroll
    for (int i = 0; i < 8; i++)
#pragma unroll
        for (int jj = 0; jj < 4; jj++) acc2[i][jj] = 0ull;

    int r0 = bm + lr;      r0 = r0 < M ? r0 : (M - 1);
    int r1 = bm + lr + 64; r1 = r1 < M ? r1 : (M - 1);

    float4 pa0, pa1, pw0, pw1;
    {
        int kg = lk;
        pa0 = *(const float4*)(A + (size_t)r0 * 384 + kg);
        pa1 = *(const float4*)(A + (size_t)r1 * 384 + kg);
        pw0 = *(const float4*)(W + (size_t)lr * K + kg);
        pw1 = *(const float4*)(W + (size_t)(lr + 64) * K + kg);
    }
    STORE_TILE(0)
    __syncthreads();

    const int ntiles = K >> 4;
    for (int t = 0; t < ntiles; t++) {
        const int cur = t & 1, nxt = cur ^ 1;
        const bool has = (t + 1) < ntiles;
        if (has) {
            int kg = ((t + 1) << 4) + lk;
            pa0 = *(const float4*)(A + (size_t)r0 * 384 + kg);
            pa1 = *(const float4*)(A + (size_t)r1 * 384 + kg);
            pw0 = *(const float4*)(W + (size_t)lr * K + kg);
            pw1 = *(const float4*)(W + (size_t)(lr + 64) * K + kg);
        }
        TILE_COMPUTE(cur)
        if (has) { STORE_TILE(nxt) }
        __syncthreads();
    }

    float bs0[8];
    *(float4*)(&bs0[0]) = *(const float4*)(bias + tx * 8);
    *(float4*)(&bs0[4]) = *(const float4*)(bias + tx * 8 + 4);
    const int gcol = 384 + 128 * sel + tx * 8;
    float w60[8], w61[8];
    *(float4*)(&w60[0]) = *(const float4*)(W6 + gcol);
    *(float4*)(&w60[4]) = *(const float4*)(W6 + gcol + 4);
    *(float4*)(&w61[0]) = *(const float4*)(W6 + 768 + gcol);
    *(float4*)(&w61[4]) = *(const float4*)(W6 + 768 + gcol + 4);

#pragma unroll
    for (int i = 0; i < 8; i++) {
        int m = bm + ty * 8 + i;
        if (m >= M) continue;
        float v[8];
#pragma unroll
        for (int jj = 0; jj < 4; jj++) {
            float lo, hi; unpack2(acc2[i][jj], lo, hi);
            v[2 * jj] = lo; v[2 * jj + 1] = hi;
        }
        float p0 = 0.f, p1 = 0.f;
#pragma unroll
        for (int j = 0; j < 8; j++) {
            float x = v[j] + bs0[j];
            x = x > 0.f ? x : 0.01f * x;
            v[j] = x;
            p0 += x * w60[j];
            p1 += x * w61[j];
        }
        float* cp = C + (size_t)m * 768 + tx * 8;
        *(float4*)(cp)     = *(float4*)(&v[0]);
        *(float4*)(cp + 4) = *(float4*)(&v[4]);
#pragma unroll
        for (int off = 8; off; off >>= 1) {
            p0 += __shfl_xor_sync(0xffffffffu, p0, off);
            p1 += __shfl_xor_sync(0xffffffffu, p1, off);
        }
        if (tx == 0) {
            outp[(size_t)m * 2 + 0] = p0;
            outp[(size_t)m * 2 + 1] = p1;
        }
    }
}

// ---------------- Y GEMM body (shared by fuseA and yabc_w2) ------------------
#define YABC_GEMM_BODY(rR, wW)                                                  \
    const float* A = (wW) == 0 ? (BIGp + 128 * (rR))                            \
                   : ((wW) == 1 ? (P1 + (size_t)(rR) * CN * 128)                \
                                : (P2 + (size_t)(rR) * CN * 128));              \
    const int lda = (wW) == 0 ? 768 : 128;                                      \
    const float* W = Wf1 + (size_t)(rR) * 128 * 128;                            \
    float* C = Y + (size_t)((rR) * 3 + (wW)) * CN * 128;                        \
    const int M = CN;                                                           \
    const int bm = blockIdx.y * 128;                                            \
    const int lr = tid >> 2;                                                    \
    const int lk = (tid & 3) << 2;                                              \
    const int ty = tid >> 4, tx = tid & 15;                                     \
    const int K = 128;                                                          \
    ull acc2[8][4];                                                             \
    _Pragma("unroll")                                                           \
    for (int i = 0; i < 8; i++)                                                 \
        _Pragma("unroll")                                                       \
        for (int jj = 0; jj < 4; jj++) acc2[i][jj] = 0ull;                      \
    int r0 = bm + lr;      r0 = r0 < M ? r0 : (M - 1);                          \
    int r1 = bm + lr + 64; r1 = r1 < M ? r1 : (M - 1);                          \
    float4 pa0, pa1, pw0, pw1;                                                  \
    {                                                                           \
        int kg = lk;                                                            \
        pa0 = *(const float4*)(A + (size_t)r0 * lda + kg);                      \
        pa1 = *(const float4*)(A + (size_t)r1 * lda + kg);                      \
        pw0 = *(const float4*)(W + (size_t)lr * K + kg);                        \
        pw1 = *(const float4*)(W + (size_t)(lr + 64) * K + kg);                 \
    }                                                                           \
    STORE_TILE(0)                                                               \
    __syncthreads();                                                            \
    _Pragma("unroll")                                                           \
    for (int t = 0; t < 8; t++) {                                               \
        const int cur = t & 1, nxt = cur ^ 1;                                   \
        const bool has = t < 7;                                                 \
        if (has) {                                                              \
            int kg = ((t + 1) << 4) + lk;                                       \
            pa0 = *(const float4*)(A + (size_t)r0 * lda + kg);                  \
            pa1 = *(const float4*)(A + (size_t)r1 * lda + kg);                  \
            pw0 = *(const float4*)(W + (size_t)lr * K + kg);                    \
            pw1 = *(const float4*)(W + (size_t)(lr + 64) * K + kg);             \
        }                                                                       \
        TILE_COMPUTE(cur)                                                       \
        if (has) { STORE_TILE(nxt) }                                            \
        __syncthreads();                                                        \
    }                                                                           \
    _Pragma("unroll")                                                           \
    for (int i = 0; i < 8; i++) {                                               \
        int m = bm + ty * 8 + i;                                                \
        if (m >= M) continue;                                                   \
        float v[8];                                                             \
        _Pragma("unroll")                                                       \
        for (int jj = 0; jj < 4; jj++) {                                        \
            float lo, hi; unpack2(acc2[i][jj], lo, hi);                         \
            v[2 * jj] = lo; v[2 * jj + 1] = hi;                                 \
        }                                                                       \
        float* cp = C + (size_t)m * 128 + tx * 8;                               \
        *(float4*)(cp)     = *(float4*)(&v[0]);                                 \
        *(float4*)(cp + 4) = *(float4*)(&v[4]);                                 \
    }

// fuseA: blockIdx.x 0..5 -> yabc (r = x/2, w = x%2); 6..8 -> prop2 (r = x-6)
__global__ __launch_bounds__(256) void fuseA_kernel(
    const float* __restrict__ BIGp,
    const float* __restrict__ P1,
    float* __restrict__ P2,
    const float* __restrict__ Wf1,
    float* __restrict__ Y,
    const int* __restrict__ csrB, const int* __restrict__ offB,
    const float* __restrict__ dinvB)
{
    const int tid = threadIdx.x;
    if (blockIdx.x >= 6) {
        // prop2 for relation r: nodes [blockIdx.y*128, +128)
        const int r = blockIdx.x - 6;
        const float* pinr = P1 + (size_t)r * CN * 128;
        float* outp = P2 + (size_t)r * CN * 128;
        const int* csr = csrB + (size_t)r * CE;
        const int* off = offB + (size_t)r * (CN + 1);
        const float* dinv = dinvB + (size_t)r * CN;
        const int wid = tid >> 5, lane = tid & 31;
        const int col = lane * 4;
        const int base = blockIdx.y * 128;
        const int end = min(base + 128, CN);
        for (int n = base + wid; n < end; n += 8)
            prop_node(n, col, pinr, 128, csr, off, dinv, outp);
        return;
    }
    __shared__ float As[2][16][128];
    __shared__ float Ws[2][16][128];
    const int rY = blockIdx.x >> 1, wY = blockIdx.x & 1;
    const float* P2c = P2;  // unused in w<2 path, silence
    (void)P2c;
    YABC_GEMM_BODY(rY, wY)
}

// yabc for w = 2 only (r = blockIdx.x)
__global__ __launch_bounds__(256) void yabc_w2_kernel(
    const float* __restrict__ BIGp,
    const float* __restrict__ P1,
    const float* __restrict__ P2,
    const float* __restrict__ Wf1,
    float* __restrict__ Y)
{
    __shared__ float As[2][16][128];
    __shared__ float Ws[2][16][128];
    const int tid = threadIdx.x;
    const int rY = blockIdx.x;
    YABC_GEMM_BODY(rY, 2)
}

// ---------------- 3-way lin5 GEMM -> out partials only -----------------------
__global__ __launch_bounds__(256) void lin5o_kernel(
    const float* __restrict__ RES,
    const float* __restrict__ W5,
    const float* __restrict__ b5,
    const float* __restrict__ W6,
    float* __restrict__ OUTP)
{
    __shared__ float As[2][16][128];
    __shared__ float Ws[2][16][128];

    const int r = blockIdx.x;
    const float* A = RES + (size_t)r * CN * 128;
    const float* W = W5 + (size_t)r * 128 * 128;
    const float* bias = b5 + (size_t)r * 128;
    float* outp = OUTP + (size_t)(3 + r) * CN * 2;

    const int M = CN;
    const int bm = blockIdx.y * 128;
    const int tid = threadIdx.x;
    const int lr = tid >> 2;
    const int lk = (tid & 3) << 2;
    const int ty = tid >> 4, tx = tid & 15;
    const int K = 128;

    ull acc2[8][4];
#pragma unroll
    for (int i = 0; i < 8; i++)
#pragma unroll
        for (int jj = 0; jj < 4; jj++) acc2[i][jj] = 0ull;

    int r0 = bm + lr;      r0 = r0 < M ? r0 : (M - 1);
    int r1 = bm + lr + 64; r1 = r1 < M ? r1 : (M - 1);

    float4 pa0, pa1, pw0, pw1;
    {
        int kg = lk;
        pa0 = *(const float4*)(A + (size_t)r0 * 128 + kg);
        pa1 = *(const float4*)(A + (size_t)r1 * 128 + kg);
        pw0 = *(const float4*)(W + (size_t)lr * K + kg);
        pw1 = *(const float4*)(W + (size_t)(lr + 64) * K + kg);
    }
    STORE_TILE(0)
    __syncthreads();

#pragma unroll
    for (int t = 0; t < 8; t++) {
        const int cur = t & 1, nxt = cur ^ 1;
        const bool has = t < 7;
        if (has) {
            int kg = ((t + 1) << 4) + lk;
            pa0 = *(const float4*)(A + (size_t)r0 * 128 + kg);
            pa1 = *(const float4*)(A + (size_t)r1 * 128 + kg);
            pw0 = *(const float4*)(W + (size_t)lr * K + kg);
            pw1 = *(const float4*)(W + (size_t)(lr + 64) * K + kg);
        }
        TILE_COMPUTE(cur)
        if (has) { STORE_TILE(nxt) }
        __syncthreads();
    }

    float bs0[8];
    *(float4*)(&bs0[0]) = *(const float4*)(bias + tx * 8);
    *(float4*)(&bs0[4]) = *(const float4*)(bias + tx * 8 + 4);
    const int gcol = 128 * r + tx * 8;
    float w60[8], w61[8];
    *(float4*)(&w60[0]) = *(const float4*)(W6 + gcol);
    *(float4*)(&w60[4]) = *(const float4*)(W6 + gcol + 4);
    *(float4*)(&w61[0]) = *(const float4*)(W6 + 768 + gcol);
    *(float4*)(&w61[4]) = *(const float4*)(W6 + 768 + gcol + 4);

#pragma unroll
    for (int i = 0; i < 8; i++) {
        int m = bm + ty * 8 + i;
        if (m >= M) continue;
        float p0 = 0.f, p1 = 0.f;
#pragma unroll
        for (int jj = 0; jj < 4; jj++) {
            float lo, hi; unpack2(acc2[i][jj], lo, hi);
            float x0 = lo + bs0[2 * jj];
            float x1 = hi + bs0[2 * jj + 1];
            x0 = x0 > 0.f ? x0 : 0.01f * x0;
            x1 = x1 > 0.f ? x1 : 0.01f * x1;
            p0 += x0 * w60[2 * jj] + x1 * w60[2 * jj + 1];
            p1 += x0 * w61[2 * jj] + x1 * w61[2 * jj + 1];
        }
#pragma unroll
        for (int off = 8; off; off >>= 1) {
            p0 += __shfl_xor_sync(0xffffffffu, p0, off);
            p1 += __shfl_xor_sync(0xffffffffu, p1, off);
        }
        if (tx == 0) {
            outp[(size_t)m * 2 + 0] = p0;
            outp[(size_t)m * 2 + 1] = p1;
        }
    }
}

// ---------------- fused dual-LSTM step kernel + CSR piggyback -----------------
__device__ __forceinline__ float sigf(float x) { return 1.f / (1.f + expf(-x)); }

__global__ __launch_bounds__(256, 2) void lstm_step2_kernel(
    const float* __restrict__ Xv, const float* __restrict__ Xs, int ldx,
    const float* __restrict__ Hv, const float* __restrict__ Hs,
    const float* __restrict__ Wcv, const float* __restrict__ Wcs,
    const float* __restrict__ bcv, const float* __restrict__ bcs,
    float* __restrict__ Cv, float* __restrict__ Cs,
    float* __restrict__ Hvo, float* __restrict__ Hso,
    int aux_mode,
    const int* __restrict__ srcB, const int* __restrict__ dstB,
    float* __restrict__ degB, int* __restrict__ offB, int* __restrict__ curB,
    float* __restrict__ dinvB, int* __restrict__ csrB)
{
    __shared__ float As[2][16][128];
    __shared__ float Ws[2][16][128];
    __shared__ int part[256];

    const int tid = threadIdx.x;

    if (blockIdx.x == 4) {
        if (aux_mode == 1) {
            if (blockIdx.y < 128) {
                size_t idx = (size_t)blockIdx.y * 256 + tid;
                const size_t stride = (size_t)128 * 256;
                for (; idx < (size_t)3 * CE; idx += stride) {
                    int r = (int)(idx / CE);
                    atomicAdd(&degB[(size_t)r * CN + dstB[idx]], 1.0f);
                }
            }
        } else if (aux_mode == 2) {
            const int r = blockIdx.y;
            if (r < 3) {
                const float* deg = degB + (size_t)r * CN;
                int* off = offB + (size_t)r * (CN + 1);
                int* cur = curB + (size_t)r * CN;
                float* dinv = dinvB + (size_t)r * CN;
                const int chunk = (CN + 255) / 256;
                const int start = tid * chunk;
                const int end = min(start + chunk, CN);
                int s = 0;
                for (int i = start; i < end; i++) s += (int)deg[i];
                part[tid] = s;
                __syncthreads();
                for (int d = 1; d < 256; d <<= 1) {
                    int v = (tid >= d) ? part[tid - d] : 0;
                    __syncthreads();
                    part[tid] += v;
                    __syncthreads();
                }
                int pre = (tid == 0) ? 0 : part[tid - 1];
                for (int i = start; i < end; i++) {
                    off[i] = pre;
                    cur[i] = pre;
                    float dg = deg[i];
                    dinv[i] = rsqrtf(fmaxf(dg, 1.0f));
                    pre += (int)dg;
                }
                if (tid == 255) off[CN] = pre;
            }
        } else if (aux_mode == 3) {
            if (blockIdx.y < 128) {
                size_t idx = (size_t)blockIdx.y * 256 + tid;
                const size_t stride = (size_t)128 * 256;
                for (; idx < (size_t)3 * CE; idx += stride) {
                    int r = (int)(idx / CE);
                    int d = dstB[idx];
                    int pos = atomicAdd(&curB[(size_t)r * CN + d], 1);
                    csrB[(size_t)r * CE + pos] = srcB[idx];
                }
            }
        }
        return;
    }

    const int sel = blockIdx.x >> 1;
    const float* X   = sel ? Xs  : Xv;
    const float* Hin = sel ? Hs  : Hv;
    const float* Wc  = sel ? Wcs : Wcv;
    const float* bc  = sel ? bcs : bcv;
    float* Cst  = sel ? Cs  : Cv;
    float* Hout = sel ? Hso : Hvo;

    const int M = CN;
    const int bm = blockIdx.y * 128;
    const int bn = (blockIdx.x & 1) * 128;
    const int lr = tid >> 2;
    const int lk = (tid & 3) << 2;
    const int ty = tid >> 4, tx = tid & 15;

    ull acc2[8][4];
#pragma unroll
    for (int i = 0; i < 8; i++)
#pragma unroll
        for (int jj = 0; jj < 4; jj++) acc2[i][jj] = 0ull;

    int r0 = bm + lr;      r0 = r0 < M ? r0 : (M - 1);
    int r1 = bm + lr + 64; r1 = r1 < M ? r1 : (M - 1);

    float4 pa0, pa1, pw0, pw1;
    {
        int kg = lk;
        pa0 = (kg < 64) ? *(const float4*)(X + (size_t)r0 * ldx + kg)
                        : *(const float4*)(Hin + (size_t)r0 * 64 + (kg - 64));
        pa1 = (kg < 64) ? *(const float4*)(X + (size_t)r1 * ldx + kg)
                        : *(const float4*)(Hin + (size_t)r1 * 64 + (kg - 64));
        pw0 = *(const float4*)(Wc + (size_t)(bn + lr) * 128 + kg);
        pw1 = *(const float4*)(Wc + (size_t)(bn + lr + 64) * 128 + kg);
    }
    STORE_TILE(0)
    __syncthreads();

#pragma unroll
    for (int t = 0; t < 8; t++) {
        const int cur = t & 1, nxt = cur ^ 1;
        const bool has = t < 7;
        if (has) {
            int kg = ((t + 1) << 4) + lk;
            pa0 = (kg < 64) ? *(const float4*)(X + (size_t)r0 * ldx + kg)
                            : *(const float4*)(Hin + (size_t)r0 * 64 + (kg - 64));
            pa1 = (kg < 64) ? *(const float4*)(X + (size_t)r1 * ldx + kg)
                            : *(const float4*)(Hin + (size_t)r1 * 64 + (kg - 64));
            pw0 = *(const float4*)(Wc + (size_t)(bn + lr) * 128 + kg);
            pw1 = *(const float4*)(Wc + (size_t)(bn + lr + 64) * 128 + kg);
        }
        TILE_COMPUTE(cur)
        if (has) { STORE_TILE(nxt) }
        __syncthreads();
    }

    const int colbase = bn + tx * 8;
    const int u0 = colbase >> 2;
    float bb[8];
    *(float4*)(&bb[0]) = *(const float4*)(bc + colbase);
    *(float4*)(&bb[4]) = *(const float4*)(bc + colbase + 4);

#pragma unroll
    for (int i = 0; i < 8; i++) {
        int m = bm + ty * 8 + i;
        if (m >= M) continue;
        float g[8];
#pragma unroll
        for (int jj = 0; jj < 4; jj++) {
            float lo, hi; unpack2(acc2[i][jj], lo, hi);
            g[2 * jj] = lo + bb[2 * jj]; g[2 * jj + 1] = hi + bb[2 * jj + 1];
        }
        float2 cold = *(float2*)(Cst + (size_t)m * 64 + u0);
        float c0 = sigf(g[1]) * cold.x + sigf(g[0]) * tanhf(g[2]);
        float c1 = sigf(g[5]) * cold.y + sigf(g[4]) * tanhf(g[6]);
        float2 cn = make_float2(c0, c1);
        float2 hn = make_float2(sigf(g[3]) * tanhf(c0), sigf(g[7]) * tanhf(c1));
        *(float2*)(Cst + (size_t)m * 64 + u0) = cn;
        *(float2*)(Hout + (size_t)m * 64 + u0) = hn;
    }
}

// ---------------- small kernels ----------------
__global__ void zero_kernel(float* p, size_t n)
{
    size_t i = (size_t)blockIdx.x * blockDim.x + threadIdx.x;
    size_t stride = (size_t)gridDim.x * blockDim.x;
    for (; i < n; i += stride) p[i] = 0.f;
}

__global__ void prep_kernel(const float* __restrict__ Wih_v, const float* __restrict__ Whh_v,
                            const float* __restrict__ bih_v, const float* __restrict__ bhh_v,
                            const float* __restrict__ Wih_s, const float* __restrict__ Whh_s,
                            const float* __restrict__ bih_s, const float* __restrict__ bhh_s,
                            float* __restrict__ S)
{
    int idx = blockIdx.x * blockDim.x + threadIdx.x;
    if (idx < 256 * 128) {
        int o = idx >> 7, k = idx & 127;
        int u = o >> 2, g = o & 3;
        int orow = g * 64 + u;
        S[OFF_WCV + idx] = (k < 64) ? Wih_v[orow * 64 + k] : Whh_v[orow * 64 + (k - 64)];
        S[OFF_WCS + idx] = (k < 64) ? Wih_s[orow * 64 + k] : Whh_s[orow * 64 + (k - 64)];
        if (idx < 256) {
            int uu = idx >> 2, gg = idx & 3;
            int ob = gg * 64 + uu;
            S[OFF_BCV + idx] = bih_v[ob] + bhh_v[ob];
            S[OFF_BCS + idx] = bih_s[ob] + bhh_s[ob];
        }
    }
}

// build W3P / W4P and zero the deg arrays (grid-stride tail)
__global__ void prep2_kernel(const float* __restrict__ W3, const float* __restrict__ W4,
                             float* __restrict__ S)
{
    int idx = blockIdx.x * blockDim.x + threadIdx.x;
    if (idx < 128 * 384) {
        int o = idx / 384, k = idx % 384;
        float v;
        if (k < 128)       v = W4[o * 512 + k];
        else if (k < 256)  v = W4[o * 512 + k] + W4[o * 512 + k + 256];
        else               v = W4[o * 512 + k];
        S[OFF_W4P + o * 384 + k] = v;
    }
    if (idx < 128 * 256) {
        int o = idx >> 8, k = idx & 255;
        float v = (k < 128) ? W3[o * 256 + 128 + k] : W3[o * 256 + (k - 128)];
        S[OFF_W3P + o * 256 + k] = v;
    }
    for (size_t i = idx; i < (size_t)3 * CN; i += (size_t)gridDim.x * blockDim.x)
        S[OFF_DEG + i] = 0.f;
}

// batched gather propagation hop1, grid.y = r
__global__ __launch_bounds__(256) void prop3_kernel(
    const float* __restrict__ pin, int ldin, size_t pin_rstride,
    const int* __restrict__ csrB, const int* __restrict__ offB,
    const float* __restrict__ dinvB, float* __restrict__ outB)
{
    const int r = blockIdx.y;
    const int n = blockIdx.x * 8 + (threadIdx.x >> 5);
    if (n >= CN) return;
    const int lane = threadIdx.x & 31;
    const int col = lane * 4;
    prop_node(n, col, pin + (size_t)r * pin_rstride, ldin,
              csrB + (size_t)r * CE, offB + (size_t)r * (CN + 1),
              dinvB + (size_t)r * CN, outB + (size_t)r * CN * 128);
}

// combine batched over relations: grid.y = r
__global__ __launch_bounds__(256) void attn_comb3_kernel(
    const float* __restrict__ YB,
    const float* __restrict__ BIGp,
    const float* __restrict__ P1B,
    const float* __restrict__ P2B,
    const float* __restrict__ bf1,
    const float* __restrict__ w2,
    float* __restrict__ resB)
{
    const int r = blockIdx.y;
    const int n = blockIdx.x * 8 + (threadIdx.x >> 5);
    if (n >= CN) return;
    const int lane = threadIdx.x & 31;
    const int col = lane * 4;

    const float* Y = YB + (size_t)r * 3 * CN * 128;
    const float* P0 = BIGp + 128 * r;
    const float* P1 = P1B + (size_t)r * CN * 128;
    const float* P2 = P2B + (size_t)r * CN * 128;

    float4 ya = *(const float4*)(Y + (size_t)n * 128 + col);
    float4 yb = *(const float4*)(Y + (size_t)CN * 128 + (size_t)n * 128 + col);
    float4 yc = *(const float4*)(Y + (size_t)2 * CN * 128 + (size_t)n * 128 + col);
    float4 bf = *(const float4*)(bf1 + (size_t)r * 128 + col);
    float4 wl = *(const float4*)(w2 + (size_t)r * 128 + col);

    float sc[5];
#pragma unroll
    for (int f = 0; f < 5; f++) {
        float t0 = c_th0[f], t1 = c_th1[f], t2 = c_th2[f];
        float gx = t0 * ya.x + t1 * yb.x + t2 * yc.x + bf.x;
        float gy = t0 * ya.y + t1 * yb.y + t2 * yc.y + bf.y;
        float gz = t0 * ya.z + t1 * yb.z + t2 * yc.z + bf.z;
        float gw = t0 * ya.w + t1 * yb.w + t2 * yc.w + bf.w;
        float p = tanhf(gx) * wl.x + tanhf(gy) * wl.y + tanhf(gz) * wl.z + tanhf(gw) * wl.w;
#pragma unroll
        for (int off = 16; off; off >>= 1) p += __shfl_xor_sync(0xffffffffu, p, off);
        sc[f] = p;
    }
    float mx = sc[0];
#pragma unroll
    for (int f = 1; f < 5; f++) mx = fmaxf(mx, sc[f]);
    float e[5], s = 0.f;
#pragma unroll
    for (int f = 0; f < 5; f++) { e[f] = expf(sc[f] - mx); s += e[f]; }
    float inv = 1.f / s;
    float ca = 0.f, cb = 0.f, cc = 0.f;
#pragma unroll
    for (int f = 0; f < 5; f++) {
        float w = e[f] * inv;
        ca += w * c_th0[f]; cb += w * c_th1[f]; cc += w * c_th2[f];
    }
    float4 a = *(const float4*)(P0 + (size_t)n * 768 + col);
    float4 b = *(const float4*)(P1 + (size_t)n * 128 + col);
    float4 c = *(const float4*)(P2 + (size_t)n * 128 + col);
    float4 rr = make_float4(ca * a.x + cb * b.x + cc * c.x,
                            ca * a.y + cb * b.y + cc * c.y,
                            ca * a.z + cb * b.z + cc * c.z,
                            ca * a.w + cb * b.w + cc * c.w);
    *(float4*)(resB + (size_t)r * CN * 128 + (size_t)n * 128 + col) = rr;
}

// out[n][c] = b6[c] + sum over 6 partials
__global__ void sumout_kernel(const float* __restrict__ OUTP,
                              const float* __restrict__ b6,
                              float* __restrict__ out)
{
    int n = blockIdx.x * blockDim.x + threadIdx.x;
    if (n >= CN) return;
    float o0 = b6[0], o1 = b6[1];
#pragma unroll
    for (int p = 0; p < 6; p++) {
        o0 += OUTP[(size_t)p * CN * 2 + (size_t)n * 2 + 0];
        o1 += OUTP[(size_t)p * CN * 2 + (size_t)n * 2 + 1];
    }
    out[(size_t)n * 2 + 0] = o0;
    out[(size_t)n * 2 + 1] = o1;
}

// ---------------- orchestration ----------------
extern "C" void kernel_launch(void* const* d_in, const int* in_sizes, int n_in,
                              void* d_out, int out_size)
{
    const float* voc    = (const float*)d_in[0];
    const float* sms    = (const float*)d_in[1];
    const float* pers   = (const float*)d_in[2];
    const float* Wih_v  = (const float*)d_in[3];
    const float* Whh_v  = (const float*)d_in[4];
    const float* bih_v  = (const float*)d_in[5];
    const float* bhh_v  = (const float*)d_in[6];
    const float* Wih_s  = (const float*)d_in[7];
    const float* Whh_s  = (const float*)d_in[8];
    const float* bih_s  = (const float*)d_in[9];
    const float* bhh_s  = (const float*)d_in[10];
    const float* W_lin  = (const float*)d_in[11];
    const float* b_lin  = (const float*)d_in[12];
    const float* W_lin1 = (const float*)d_in[13];
    const float* b_lin1 = (const float*)d_in[14];
    const float* W_pers = (const float*)d_in[15];
    const float* b_pers = (const float*)d_in[16];
    const float* W_lin2 = (const float*)d_in[17];
    const float* b_lin2 = (const float*)d_in[18];
    const float* W_lin3 = (const float*)d_in[19];
    const float* b_lin3 = (const float*)d_in[20];
    const float* W_lin4 = (const float*)d_in[21];
    const float* b_lin4 = (const float*)d_in[22];
    const float* W_lin5 = (const float*)d_in[23];
    const float* b_lin5 = (const float*)d_in[24];
    const float* Wf1    = (const float*)d_in[25];
    const float* bf1    = (const float*)d_in[26];
    const float* Wf2    = (const float*)d_in[27];
    const float* W_lin6 = (const float*)d_in[28];
    const float* b_lin6 = (const float*)d_in[29];
    const int*   src    = (const int*)d_in[30];
    const int*   dst    = (const int*)d_in[31];
    float* out = (float*)d_out;

    float* S = nullptr;
    cudaGetSymbolAddress((void**)&S, g_scratch);
    int* csr = nullptr; cudaGetSymbolAddress((void**)&csr, g_csr);
    int* offp = nullptr; cudaGetSymbolAddress((void**)&offp, g_off);
    int* curp = nullptr; cudaGetSymbolAddress((void**)&curp, g_cur);

    // prep + derived weights (+ deg zero) + zero states
    prep_kernel<<<(256 * 128 + 255) / 256, 256>>>(Wih_v, Whh_v, bih_v, bhh_v,
                                                  Wih_s, Whh_s, bih_s, bhh_s, S);
    prep2_kernel<<<(128 * 384 + 255) / 256, 256>>>(W_lin3, W_lin4, S);
    zero_kernel<<<4096, 256>>>(S + OFF_HV0, (size_t)6 * CN * 64);

    // ---- LSTMs: 16 steps; steps 0-2 piggyback the CSR build ----
    const int ygrid = (CN + 127) / 128;
    for (int t = 0; t < CT; t++) {
        const float* hv_in  = S + ((t & 1) ? OFF_HV1 : OFF_HV0);
        float*       hv_out = S + ((t & 1) ? OFF_HV0 : OFF_HV1);
        const float* hs_in  = S + ((t & 1) ? OFF_HS1 : OFF_HS0);
        float*       hs_out = S + ((t & 1) ? OFF_HS0 : OFF_HS1);
        const int aux = (t == 0) ? 1 : (t == 1) ? 2 : (t == 2) ? 3 : 0;
        dim3 lgrid(aux ? 5 : 4, ygrid);
        lstm_step2_kernel<<<lgrid, 256>>>(voc + (size_t)t * 64, sms + (size_t)t * 64, CT * 64,
                                          hv_in, hs_in,
                                          S + OFF_WCV, S + OFF_WCS,
                                          S + OFF_BCV, S + OFF_BCS,
                                          S + OFF_CV, S + OFF_CS,
                                          hv_out, hs_out,
                                          aux, src, dst,
                                          S + OFF_DEG, offp, curp,
                                          S + OFF_DINV, csr);
    }

    // ---- projections (batched); projB also emits out partials for xin ----
    projA_kernel<<<dim3(3, ygrid), 256>>>(S + OFF_HV0, S + OFF_HS0, pers,
                                          W_lin, b_lin, W_lin1, b_lin1,
                                          W_pers, b_pers, S + OFF_XCAT);
    projB_kernel<<<dim3(3, ygrid), 256>>>(S + OFF_XCAT,
                                          W_lin2, b_lin2,
                                          S + OFF_W3P, b_lin3,
                                          S + OFF_W4P, b_lin4,
                                          W_lin6,
                                          S + OFF_BIG, S + OFF_OUTP);

    // ---- relation graphs ----
    const int pgrid = (CN + 7) / 8;
    const float* BIGp = S + OFF_BIG + 384;

    // hop 1
    prop3_kernel<<<dim3(pgrid, 3), 256>>>(BIGp, 768, 128,
                                          csr, offp, S + OFF_DINV, S + OFF_P1);
    // hop 2 fused with the 6 prop2-independent Y GEMMs (w in {0,1})
    fuseA_kernel<<<dim3(9, ygrid), 256>>>(BIGp, S + OFF_P1, S + OFF_P2,
                                          Wf1, S + OFF_Y,
                                          csr, offp, S + OFF_DINV);
    // remaining Y GEMMs (w = 2, needs P2)
    yabc_w2_kernel<<<dim3(3, ygrid), 256>>>(BIGp, S + OFF_P1, S + OFF_P2,
                                            Wf1, S + OFF_Y);

    attn_comb3_kernel<<<dim3(pgrid, 3), 256>>>(S + OFF_Y, BIGp, S + OFF_P1, S + OFF_P2,
                                               bf1, Wf2, S + OFF_RES);

    // lin5 -> out partials only (hall never materialized)
    lin5o_kernel<<<dim3(3, ygrid), 256>>>(S + OFF_RES, W_lin5, b_lin5,
                                          W_lin6, S + OFF_OUTP);

    // ---- final head: sum 6 partials + bias ----
    sumout_kernel<<<(CN + 255) / 256, 256>>>(S + OFF_OUTP, b_lin6, out);
}

// round 17
// speedup vs baseline: 1.0309x; 1.0309x over previous
#include <cuda_runtime.h>
#include <math.h>
#include <stdint.h>

// Problem constants
#define CN 50000
#define CE 800000
#define CR 3
#define CT 16

typedef unsigned long long ull;

__device__ __forceinline__ ull pack2(float lo, float hi) {
    ull r; asm("mov.b64 %0, {%1,%2};" : "=l"(r) : "f"(lo), "f"(hi)); return r;
}
__device__ __forceinline__ ull fma2(ull a, ull b, ull c) {
    ull d; asm("fma.rn.f32x2 %0, %1, %2, %3;" : "=l"(d) : "l"(a), "l"(b), "l"(c)); return d;
}
__device__ __forceinline__ void unpack2(ull v, float& lo, float& hi) {
    asm("mov.b64 {%0,%1}, %2;" : "=f"(lo), "=f"(hi) : "l"(v));
}

// ---------------- scratch layout (floats) ----------------
constexpr size_t SZ_WCAT = 256 * 128;
constexpr size_t OFF_WCV = 0;
constexpr size_t OFF_WCS = OFF_WCV + SZ_WCAT;
constexpr size_t OFF_BCV = OFF_WCS + SZ_WCAT;
constexpr size_t OFF_BCS = OFF_BCV + 256;
constexpr size_t OFF_W3P = OFF_BCS + 256;                 // 128*256 (lin3, k-perm)
constexpr size_t OFF_W4P = OFF_W3P + 128 * 256;           // 128*384 (lin4, xp-combined)
constexpr size_t OFF_HV0 = OFF_W4P + 128 * 384;           // N*64 each
constexpr size_t OFF_HV1 = OFF_HV0 + (size_t)CN * 64;
constexpr size_t OFF_HS0 = OFF_HV1 + (size_t)CN * 64;
constexpr size_t OFF_HS1 = OFF_HS0 + (size_t)CN * 64;
constexpr size_t OFF_CV  = OFF_HS1 + (size_t)CN * 64;
constexpr size_t OFF_CS  = OFF_CV + (size_t)CN * 64;
constexpr size_t OFF_XCAT= OFF_CS + (size_t)CN * 64;      // [xv|xp|xs] N*384
constexpr size_t OFF_BIG = OFF_XCAT + (size_t)CN * 384;   // [unused(384) | xin0..2] N*768
constexpr size_t OFF_P1  = OFF_BIG + (size_t)CN * 768;    // 3 x N*128
constexpr size_t OFF_P2  = OFF_P1 + (size_t)3 * CN * 128; // 3 x N*128
constexpr size_t OFF_Y   = OFF_P2 + (size_t)3 * CN * 128; // 3 x 3 x N*128
constexpr size_t OFF_RES = OFF_Y + (size_t)9 * CN * 128;  // 3 x N*128
constexpr size_t OFF_DEG = OFF_RES + (size_t)3 * CN * 128;// 3 x N
constexpr size_t OFF_DINV= OFF_DEG + (size_t)3 * CN;      // 3 x N
constexpr size_t OFF_OUTP= OFF_DINV + (size_t)3 * CN;     // 6 x N x 2 partials
constexpr size_t SCRATCH_TOTAL = OFF_OUTP + (size_t)6 * CN * 2 + 64;

__device__ float g_scratch[SCRATCH_TOTAL];
__device__ int g_csr[3 * CE];
__device__ int g_off[3 * (CN + 1)];
__device__ int g_cur[3 * CN];

// THETAS coefficients on (p0, p1, p2)
__device__ __constant__ float c_th0[5] = {0.8f, 3.0f, 0.0f, 0.0f, -0.2f};
__device__ __constant__ float c_th1[5] = {-0.5f, -3.0f, 3.0f, 0.0f, 0.5f};
__device__ __constant__ float c_th2[5] = {0.0f, 0.75f, -1.5f, 0.75f, 0.0f};

// =====================================================================
// FFMA2 GEMM core (PROVEN shape)
// =====================================================================
#define TILE_COMPUTE(cur)                                                      \
    _Pragma("unroll")                                                          \
    for (int kk = 0; kk < 16; kk++) {                                          \
        float a[8]; ull b2[4];                                                 \
        *(float4*)(&a[0]) = *(const float4*)(&As[cur][kk][ty * 8]);            \
        *(float4*)(&a[4]) = *(const float4*)(&As[cur][kk][ty * 8 + 4]);        \
        {                                                                      \
            const ulonglong2* wp = (const ulonglong2*)(&Ws[cur][kk][tx * 8]);  \
            ulonglong2 w0 = wp[0]; ulonglong2 w1 = wp[1];                      \
            b2[0] = w0.x; b2[1] = w0.y; b2[2] = w1.x; b2[3] = w1.y;            \
        }                                                                      \
        _Pragma("unroll")                                                      \
        for (int i = 0; i < 8; i++) {                                          \
            ull ai = pack2(a[i], a[i]);                                        \
            _Pragma("unroll")                                                  \
            for (int jj = 0; jj < 4; jj++)                                     \
                acc2[i][jj] = fma2(ai, b2[jj], acc2[i][jj]);                   \
        }                                                                      \
    }

#define STORE_TILE(buf)                                                                         \
    As[buf][lk+0][lr] = pa0.x; As[buf][lk+1][lr] = pa0.y;                                       \
    As[buf][lk+2][lr] = pa0.z; As[buf][lk+3][lr] = pa0.w;                                       \
    As[buf][lk+0][lr+64] = pa1.x; As[buf][lk+1][lr+64] = pa1.y;                                 \
    As[buf][lk+2][lr+64] = pa1.z; As[buf][lk+3][lr+64] = pa1.w;                                 \
    Ws[buf][lk+0][lr] = pw0.x; Ws[buf][lk+1][lr] = pw0.y;                                       \
    Ws[buf][lk+2][lr] = pw0.z; Ws[buf][lk+3][lr] = pw0.w;                                       \
    Ws[buf][lk+0][lr+64] = pw1.x; Ws[buf][lk+1][lr+64] = pw1.y;                                 \
    Ws[buf][lk+2][lr+64] = pw1.z; Ws[buf][lk+3][lr+64] = pw1.w;

// gather one node's propagation (warp-wide), ldin-strided input
__device__ __forceinline__ void prop_node(
    int n, int col, const float* __restrict__ pinr, int ldin,
    const int* __restrict__ csr, const int* __restrict__ off,
    const float* __restrict__ dinv, float* __restrict__ outp)
{
    float4 acc = make_float4(0.f, 0.f, 0.f, 0.f);
    const int s0 = off[n], s1 = off[n + 1];
    int e = s0;
    for (; e + 4 <= s1; e += 4) {
        int sn0 = csr[e], sn1 = csr[e + 1], sn2 = csr[e + 2], sn3 = csr[e + 3];
        float d0 = __ldg(&dinv[sn0]), d1 = __ldg(&dinv[sn1]);
        float d2 = __ldg(&dinv[sn2]), d3 = __ldg(&dinv[sn3]);
        float4 v0 = *(const float4*)(pinr + (size_t)sn0 * ldin + col);
        float4 v1 = *(const float4*)(pinr + (size_t)sn1 * ldin + col);
        float4 v2 = *(const float4*)(pinr + (size_t)sn2 * ldin + col);
        float4 v3 = *(const float4*)(pinr + (size_t)sn3 * ldin + col);
        acc.x += v0.x * d0 + v1.x * d1 + v2.x * d2 + v3.x * d3;
        acc.y += v0.y * d0 + v1.y * d1 + v2.y * d2 + v3.y * d3;
        acc.z += v0.z * d0 + v1.z * d1 + v2.z * d2 + v3.z * d3;
        acc.w += v0.w * d0 + v1.w * d1 + v2.w * d2 + v3.w * d3;
    }
    for (; e < s1; e++) {
        int sn = csr[e];
        float ds = __ldg(&dinv[sn]);
        float4 v = *(const float4*)(pinr + (size_t)sn * ldin + col);
        acc.x += v.x * ds; acc.y += v.y * ds; acc.z += v.z * ds; acc.w += v.w * ds;
    }
    const float dn = dinv[n];
    float4 pv = *(const float4*)(pinr + (size_t)n * ldin + col);
    float4 o = make_float4(pv.x - acc.x * dn, pv.y - acc.y * dn,
                           pv.z - acc.z * dn, pv.w - acc.w * dn);
    *(float4*)(outp + (size_t)n * 128 + col) = o;
}

// ---------------- batched projection A ---------------------------------------
__global__ __launch_bounds__(256) void projA_kernel(
    const float* __restrict__ HV, const float* __restrict__ HS,
    const float* __restrict__ PERS,
    const float* __restrict__ Wl, const float* __restrict__ bl,
    const float* __restrict__ Wl1, const float* __restrict__ bl1,
    const float* __restrict__ Wp, const float* __restrict__ bp,
    float* __restrict__ XCAT)
{
    __shared__ float As[2][16][128];
    __shared__ float Ws[2][16][128];

    const int sel = blockIdx.x;
    const float* A = sel == 0 ? HV : (sel == 1 ? PERS : HS);
    const int lda = sel == 1 ? 32 : 64;
    const int K = lda;
    const float* W = sel == 0 ? Wl : (sel == 1 ? Wp : Wl1);
    const float* bias = sel == 0 ? bl : (sel == 1 ? bp : bl1);
    float* C = XCAT + 128 * sel;

    const int M = CN;
    const int bm = blockIdx.y * 128;
    const int tid = threadIdx.x;
    const int lr = tid >> 2;
    const int lk = (tid & 3) << 2;
    const int ty = tid >> 4, tx = tid & 15;

    ull acc2[8][4];
#pragma unroll
    for (int i = 0; i < 8; i++)
#pragma unroll
        for (int jj = 0; jj < 4; jj++) acc2[i][jj] = 0ull;

    int r0 = bm + lr;      r0 = r0 < M ? r0 : (M - 1);
    int r1 = bm + lr + 64; r1 = r1 < M ? r1 : (M - 1);

    float4 pa0, pa1, pw0, pw1;
    {
        int kg = lk;
        pa0 = *(const float4*)(A + (size_t)r0 * lda + kg);
        pa1 = *(const float4*)(A + (size_t)r1 * lda + kg);
        pw0 = *(const float4*)(W + (size_t)lr * K + kg);
        pw1 = *(const float4*)(W + (size_t)(lr + 64) * K + kg);
    }
    STORE_TILE(0)
    __syncthreads();

    const int ntiles = K >> 4;
    for (int t = 0; t < ntiles; t++) {
        const int cur = t & 1, nxt = cur ^ 1;
        const bool has = (t + 1) < ntiles;
        if (has) {
            int kg = ((t + 1) << 4) + lk;
            pa0 = *(const float4*)(A + (size_t)r0 * lda + kg);
            pa1 = *(const float4*)(A + (size_t)r1 * lda + kg);
            pw0 = *(const float4*)(W + (size_t)lr * K + kg);
            pw1 = *(const float4*)(W + (size_t)(lr + 64) * K + kg);
        }
        TILE_COMPUTE(cur)
        if (has) { STORE_TILE(nxt) }
        __syncthreads();
    }

    float bs0[8];
    *(float4*)(&bs0[0]) = *(const float4*)(bias + tx * 8);
    *(float4*)(&bs0[4]) = *(const float4*)(bias + tx * 8 + 4);

#pragma unroll
    for (int i = 0; i < 8; i++) {
        int m = bm + ty * 8 + i;
        if (m >= M) continue;
        float v[8];
#pragma unroll
        for (int jj = 0; jj < 4; jj++) {
            float lo, hi; unpack2(acc2[i][jj], lo, hi);
            v[2 * jj] = lo; v[2 * jj + 1] = hi;
        }
#pragma unroll
        for (int j = 0; j < 8; j++) {
            float x = v[j] + bs0[j];
            v[j] = x > 0.f ? x : 0.01f * x;
        }
        float* cp = C + (size_t)m * 384 + tx * 8;
        *(float4*)(cp)     = *(float4*)(&v[0]);
        *(float4*)(cp + 4) = *(float4*)(&v[4]);
    }
}

// ---------------- batched projection B + out partials -------------------------
__global__ __launch_bounds__(256) void projB_kernel(
    const float* __restrict__ XCAT,
    const float* __restrict__ Wl2, const float* __restrict__ bl2,
    const float* __restrict__ W3P, const float* __restrict__ bl3,
    const float* __restrict__ W4P, const float* __restrict__ bl4,
    const float* __restrict__ W6,
    float* __restrict__ BIG, float* __restrict__ OUTP)
{
    __shared__ float As[2][16][128];
    __shared__ float Ws[2][16][128];

    const int sel = blockIdx.x;
    const float* A = XCAT + (sel == 1 ? 128 : 0);
    const int K = sel == 2 ? 384 : 256;
    const float* W = sel == 0 ? Wl2 : (sel == 1 ? W3P : W4P);
    const float* bias = sel == 0 ? bl2 : (sel == 1 ? bl3 : bl4);
    float* C = BIG + 384 + 128 * sel;
    float* outp = OUTP + (size_t)sel * CN * 2;

    const int M = CN;
    const int bm = blockIdx.y * 128;
    const int tid = threadIdx.x;
    const int lr = tid >> 2;
    const int lk = (tid & 3) << 2;
    const int ty = tid >> 4, tx = tid & 15;

    ull acc2[8][4];
#pragma unroll
    for (int i = 0; i < 8; i++)
#pragma unroll
        for (int jj = 0; jj < 4; jj++) acc2[i][jj] = 0ull;

    int r0 = bm + lr;      r0 = r0 < M ? r0 : (M - 1);
    int r1 = bm + lr + 64; r1 = r1 < M ? r1 : (M - 1);

    float4 pa0, pa1, pw0, pw1;
    {
        int kg = lk;
        pa0 = *(const float4*)(A + (size_t)r0 * 384 + kg);
        pa1 = *(const float4*)(A + (size_t)r1 * 384 + kg);
        pw0 = *(const float4*)(W + (size_t)lr * K + kg);
        pw1 = *(const float4*)(W + (size_t)(lr + 64) * K + kg);
    }
    STORE_TILE(0)
    __syncthreads();

    const int ntiles = K >> 4;
    for (int t = 0; t < ntiles; t++) {
        const int cur = t & 1, nxt = cur ^ 1;
        const bool has = (t + 1) < ntiles;
        if (has) {
            int kg = ((t + 1) << 4) + lk;
            pa0 = *(const float4*)(A + (size_t)r0 * 384 + kg);
            pa1 = *(const float4*)(A + (size_t)r1 * 384 + kg);
            pw0 = *(const float4*)(W + (size_t)lr * K + kg);
            pw1 = *(const float4*)(W + (size_t)(lr + 64) * K + kg);
        }
        TILE_COMPUTE(cur)
        if (has) { STORE_TILE(nxt) }
        __syncthreads();
    }

    float bs0[8];
    *(float4*)(&bs0[0]) = *(const float4*)(bias + tx * 8);
    *(float4*)(&bs0[4]) = *(const float4*)(bias + tx * 8 + 4);
    const int gcol = 384 + 128 * sel + tx * 8;
    float w60[8], w61[8];
    *(float4*)(&w60[0]) = *(const float4*)(W6 + gcol);
    *(float4*)(&w60[4]) = *(const float4*)(W6 + gcol + 4);
    *(float4*)(&w61[0]) = *(const float4*)(W6 + 768 + gcol);
    *(float4*)(&w61[4]) = *(const float4*)(W6 + 768 + gcol + 4);

#pragma unroll
    for (int i = 0; i < 8; i++) {
        int m = bm + ty * 8 + i;
        if (m >= M) continue;
        float v[8];
#pragma unroll
        for (int jj = 0; jj < 4; jj++) {
            float lo, hi; unpack2(acc2[i][jj], lo, hi);
            v[2 * jj] = lo; v[2 * jj + 1] = hi;
        }
        float p0 = 0.f, p1 = 0.f;
#pragma unroll
        for (int j = 0; j < 8; j++) {
            float x = v[j] + bs0[j];
            x = x > 0.f ? x : 0.01f * x;
            v[j] = x;
            p0 += x * w60[j];
            p1 += x * w61[j];
        }
        float* cp = C + (size_t)m * 768 + tx * 8;
        *(float4*)(cp)     = *(float4*)(&v[0]);
        *(float4*)(cp + 4) = *(float4*)(&v[4]);
#pragma unroll
        for (int off = 8; off; off >>= 1) {
            p0 += __shfl_xor_sync(0xffffffffu, p0, off);
            p1 += __shfl_xor_sync(0xffffffffu, p1, off);
        }
        if (tx == 0) {
            outp[(size_t)m * 2 + 0] = p0;
            outp[(size_t)m * 2 + 1] = p1;
        }
    }
}

// ---------------- 9-way Y GEMM: Y[r][w] = P_w(r) @ Wf1[r]^T -----------------
__global__ __launch_bounds__(256) void yabc9_kernel(
    const float* __restrict__ BIGp,
    const float* __restrict__ P1,
    const float* __restrict__ P2,
    const float* __restrict__ Wf1,
    float* __restrict__ Y)
{
    __shared__ float As[2][16][128];
    __shared__ float Ws[2][16][128];

    const int sel = blockIdx.x;
    const int r = sel / 3, w = sel % 3;
    const float* A = w == 0 ? (BIGp + 128 * r)
                   : (w == 1 ? (P1 + (size_t)r * CN * 128) : (P2 + (size_t)r * CN * 128));
    const int lda = w == 0 ? 768 : 128;
    const float* W = Wf1 + (size_t)r * 128 * 128;
    float* C = Y + (size_t)sel * CN * 128;

    const int M = CN;
    const int bm = blockIdx.y * 128;
    const int tid = threadIdx.x;
    const int lr = tid >> 2;
    const int lk = (tid & 3) << 2;
    const int ty = tid >> 4, tx = tid & 15;
    const int K = 128;

    ull acc2[8][4];
#pragma unroll
    for (int i = 0; i < 8; i++)
#pragma unroll
        for (int jj = 0; jj < 4; jj++) acc2[i][jj] = 0ull;

    int r0 = bm + lr;      r0 = r0 < M ? r0 : (M - 1);
    int r1 = bm + lr + 64; r1 = r1 < M ? r1 : (M - 1);

    float4 pa0, pa1, pw0, pw1;
    {
        int kg = lk;
        pa0 = *(const float4*)(A + (size_t)r0 * lda + kg);
        pa1 = *(const float4*)(A + (size_t)r1 * lda + kg);
        pw0 = *(const float4*)(W + (size_t)lr * K + kg);
        pw1 = *(const float4*)(W + (size_t)(lr + 64) * K + kg);
    }
    STORE_TILE(0)
    __syncthreads();

#pragma unroll
    for (int t = 0; t < 8; t++) {
        const int cur = t & 1, nxt = cur ^ 1;
        const bool has = t < 7;
        if (has) {
            int kg = ((t + 1) << 4) + lk;
            pa0 = *(const float4*)(A + (size_t)r0 * lda + kg);
            pa1 = *(const float4*)(A + (size_t)r1 * lda + kg);
            pw0 = *(const float4*)(W + (size_t)lr * K + kg);
            pw1 = *(const float4*)(W + (size_t)(lr + 64) * K + kg);
        }
        TILE_COMPUTE(cur)
        if (has) { STORE_TILE(nxt) }
        __syncthreads();
    }

#pragma unroll
    for (int i = 0; i < 8; i++) {
        int m = bm + ty * 8 + i;
        if (m >= M) continue;
        float v[8];
#pragma unroll
        for (int jj = 0; jj < 4; jj++) {
            float lo, hi; unpack2(acc2[i][jj], lo, hi);
            v[2 * jj] = lo; v[2 * jj + 1] = hi;
        }
        float* cp = C + (size_t)m * 128 + tx * 8;
        *(float4*)(cp)     = *(float4*)(&v[0]);
        *(float4*)(cp + 4) = *(float4*)(&v[4]);
    }
}

// ---------------- 3-way lin5 GEMM -> out partials only -----------------------
__global__ __launch_bounds__(256) void lin5o_kernel(
    const float* __restrict__ RES,
    const float* __restrict__ W5,
    const float* __restrict__ b5,
    const float* __restrict__ W6,
    float* __restrict__ OUTP)
{
    __shared__ float As[2][16][128];
    __shared__ float Ws[2][16][128];

    const int r = blockIdx.x;
    const float* A = RES + (size_t)r * CN * 128;
    const float* W = W5 + (size_t)r * 128 * 128;
    const float* bias = b5 + (size_t)r * 128;
    float* outp = OUTP + (size_t)(3 + r) * CN * 2;

    const int M = CN;
    const int bm = blockIdx.y * 128;
    const int tid = threadIdx.x;
    const int lr = tid >> 2;
    const int lk = (tid & 3) << 2;
    const int ty = tid >> 4, tx = tid & 15;
    const int K = 128;

    ull acc2[8][4];
#pragma unroll
    for (int i = 0; i < 8; i++)
#pragma unroll
        for (int jj = 0; jj < 4; jj++) acc2[i][jj] = 0ull;

    int r0 = bm + lr;      r0 = r0 < M ? r0 : (M - 1);
    int r1 = bm + lr + 64; r1 = r1 < M ? r1 : (M - 1);

    float4 pa0, pa1, pw0, pw1;
    {
        int kg = lk;
        pa0 = *(const float4*)(A + (size_t)r0 * 128 + kg);
        pa1 = *(const float4*)(A + (size_t)r1 * 128 + kg);
        pw0 = *(const float4*)(W + (size_t)lr * K + kg);
        pw1 = *(const float4*)(W + (size_t)(lr + 64) * K + kg);
    }
    STORE_TILE(0)
    __syncthreads();

#pragma unroll
    for (int t = 0; t < 8; t++) {
        const int cur = t & 1, nxt = cur ^ 1;
        const bool has = t < 7;
        if (has) {
            int kg = ((t + 1) << 4) + lk;
            pa0 = *(const float4*)(A + (size_t)r0 * 128 + kg);
            pa1 = *(const float4*)(A + (size_t)r1 * 128 + kg);
            pw0 = *(const float4*)(W + (size_t)lr * K + kg);
            pw1 = *(const float4*)(W + (size_t)(lr + 64) * K + kg);
        }
        TILE_COMPUTE(cur)
        if (has) { STORE_TILE(nxt) }
        __syncthreads();
    }

    float bs0[8];
    *(float4*)(&bs0[0]) = *(const float4*)(bias + tx * 8);
    *(float4*)(&bs0[4]) = *(const float4*)(bias + tx * 8 + 4);
    const int gcol = 128 * r + tx * 8;
    float w60[8], w61[8];
    *(float4*)(&w60[0]) = *(const float4*)(W6 + gcol);
    *(float4*)(&w60[4]) = *(const float4*)(W6 + gcol + 4);
    *(float4*)(&w61[0]) = *(const float4*)(W6 + 768 + gcol);
    *(float4*)(&w61[4]) = *(const float4*)(W6 + 768 + gcol + 4);

#pragma unroll
    for (int i = 0; i < 8; i++) {
        int m = bm + ty * 8 + i;
        if (m >= M) continue;
        float p0 = 0.f, p1 = 0.f;
#pragma unroll
        for (int jj = 0; jj < 4; jj++) {
            float lo, hi; unpack2(acc2[i][jj], lo, hi);
            float x0 = lo + bs0[2 * jj];
            float x1 = hi + bs0[2 * jj + 1];
            x0 = x0 > 0.f ? x0 : 0.01f * x0;
            x1 = x1 > 0.f ? x1 : 0.01f * x1;
            p0 += x0 * w60[2 * jj] + x1 * w60[2 * jj + 1];
            p1 += x0 * w61[2 * jj] + x1 * w61[2 * jj + 1];
        }
#pragma unroll
        for (int off = 8; off; off >>= 1) {
            p0 += __shfl_xor_sync(0xffffffffu, p0, off);
            p1 += __shfl_xor_sync(0xffffffffu, p1, off);
        }
        if (tx == 0) {
            outp[(size_t)m * 2 + 0] = p0;
            outp[(size_t)m * 2 + 1] = p1;
        }
    }
}

// ---------------- fused dual-LSTM step kernel + CSR piggyback -----------------
__device__ __forceinline__ float sigf(float x) { return 1.f / (1.f + expf(-x)); }

__global__ __launch_bounds__(256, 2) void lstm_step2_kernel(
    const float* __restrict__ Xv, const float* __restrict__ Xs, int ldx,
    const float* __restrict__ Hv, const float* __restrict__ Hs,
    const float* __restrict__ Wcv, const float* __restrict__ Wcs,
    const float* __restrict__ bcv, const float* __restrict__ bcs,
    float* __restrict__ Cv, float* __restrict__ Cs,
    float* __restrict__ Hvo, float* __restrict__ Hso,
    int aux_mode,
    const int* __restrict__ srcB, const int* __restrict__ dstB,
    float* __restrict__ degB, int* __restrict__ offB, int* __restrict__ curB,
    float* __restrict__ dinvB, int* __restrict__ csrB)
{
    __shared__ float As[2][16][128];
    __shared__ float Ws[2][16][128];
    __shared__ int part[256];

    const int tid = threadIdx.x;

    if (blockIdx.x == 4) {
        if (aux_mode == 1) {
            if (blockIdx.y < 128) {
                size_t idx = (size_t)blockIdx.y * 256 + tid;
                const size_t stride = (size_t)128 * 256;
                for (; idx < (size_t)3 * CE; idx += stride) {
                    int r = (int)(idx / CE);
                    atomicAdd(&degB[(size_t)r * CN + dstB[idx]], 1.0f);
                }
            }
        } else if (aux_mode == 2) {
            const int r = blockIdx.y;
            if (r < 3) {
                const float* deg = degB + (size_t)r * CN;
                int* off = offB + (size_t)r * (CN + 1);
                int* cur = curB + (size_t)r * CN;
                float* dinv = dinvB + (size_t)r * CN;
                const int chunk = (CN + 255) / 256;
                const int start = tid * chunk;
                const int end = min(start + chunk, CN);
                int s = 0;
                for (int i = start; i < end; i++) s += (int)deg[i];
                part[tid] = s;
                __syncthreads();
                for (int d = 1; d < 256; d <<= 1) {
                    int v = (tid >= d) ? part[tid - d] : 0;
                    __syncthreads();
                    part[tid] += v;
                    __syncthreads();
                }
                int pre = (tid == 0) ? 0 : part[tid - 1];
                for (int i = start; i < end; i++) {
                    off[i] = pre;
                    cur[i] = pre;
                    float dg = deg[i];
                    dinv[i] = rsqrtf(fmaxf(dg, 1.0f));
                    pre += (int)dg;
                }
                if (tid == 255) off[CN] = pre;
            }
        } else if (aux_mode == 3) {
            if (blockIdx.y < 128) {
                size_t idx = (size_t)blockIdx.y * 256 + tid;
                const size_t stride = (size_t)128 * 256;
                for (; idx < (size_t)3 * CE; idx += stride) {
                    int r = (int)(idx / CE);
                    int d = dstB[idx];
                    int pos = atomicAdd(&curB[(size_t)r * CN + d], 1);
                    csrB[(size_t)r * CE + pos] = srcB[idx];
                }
            }
        }
        return;
    }

    const int sel = blockIdx.x >> 1;
    const float* X   = sel ? Xs  : Xv;
    const float* Hin = sel ? Hs  : Hv;
    const float* Wc  = sel ? Wcs : Wcv;
    const float* bc  = sel ? bcs : bcv;
    float* Cst  = sel ? Cs  : Cv;
    float* Hout = sel ? Hso : Hvo;

    const int M = CN;
    const int bm = blockIdx.y * 128;
    const int bn = (blockIdx.x & 1) * 128;
    const int lr = tid >> 2;
    const int lk = (tid & 3) << 2;
    const int ty = tid >> 4, tx = tid & 15;

    ull acc2[8][4];
#pragma unroll
    for (int i = 0; i < 8; i++)
#pragma unroll
        for (int jj = 0; jj < 4; jj++) acc2[i][jj] = 0ull;

    int r0 = bm + lr;      r0 = r0 < M ? r0 : (M - 1);
    int r1 = bm + lr + 64; r1 = r1 < M ? r1 : (M - 1);

    float4 pa0, pa1, pw0, pw1;
    {
        int kg = lk;
        pa0 = (kg < 64) ? *(const float4*)(X + (size_t)r0 * ldx + kg)
                        : *(const float4*)(Hin + (size_t)r0 * 64 + (kg - 64));
        pa1 = (kg < 64) ? *(const float4*)(X + (size_t)r1 * ldx + kg)
                        : *(const float4*)(Hin + (size_t)r1 * 64 + (kg - 64));
        pw0 = *(const float4*)(Wc + (size_t)(bn + lr) * 128 + kg);
        pw1 = *(const float4*)(Wc + (size_t)(bn + lr + 64) * 128 + kg);
    }
    STORE_TILE(0)
    __syncthreads();

#pragma unroll
    for (int t = 0; t < 8; t++) {
        const int cur = t & 1, nxt = cur ^ 1;
        const bool has = t < 7;
        if (has) {
            int kg = ((t + 1) << 4) + lk;
            pa0 = (kg < 64) ? *(const float4*)(X + (size_t)r0 * ldx + kg)
                            : *(const float4*)(Hin + (size_t)r0 * 64 + (kg - 64));
            pa1 = (kg < 64) ? *(const float4*)(X + (size_t)r1 * ldx + kg)
                            : *(const float4*)(Hin + (size_t)r1 * 64 + (kg - 64));
            pw0 = *(const float4*)(Wc + (size_t)(bn + lr) * 128 + kg);
            pw1 = *(const float4*)(Wc + (size_t)(bn + lr + 64) * 128 + kg);
        }
        TILE_COMPUTE(cur)
        if (has) { STORE_TILE(nxt) }
        __syncthreads();
    }

    const int colbase = bn + tx * 8;
    const int u0 = colbase >> 2;
    float bb[8];
    *(float4*)(&bb[0]) = *(const float4*)(bc + colbase);
    *(float4*)(&bb[4]) = *(const float4*)(bc + colbase + 4);

#pragma unroll
    for (int i = 0; i < 8; i++) {
        int m = bm + ty * 8 + i;
        if (m >= M) continue;
        float g[8];
#pragma unroll
        for (int jj = 0; jj < 4; jj++) {
            float lo, hi; unpack2(acc2[i][jj], lo, hi);
            g[2 * jj] = lo + bb[2 * jj]; g[2 * jj + 1] = hi + bb[2 * jj + 1];
        }
        float2 cold = *(float2*)(Cst + (size_t)m * 64 + u0);
        float c0 = sigf(g[1]) * cold.x + sigf(g[0]) * tanhf(g[2]);
        float c1 = sigf(g[5]) * cold.y + sigf(g[4]) * tanhf(g[6]);
        float2 cn = make_float2(c0, c1);
        float2 hn = make_float2(sigf(g[3]) * tanhf(c0), sigf(g[7]) * tanhf(c1));
        *(float2*)(Cst + (size_t)m * 64 + u0) = cn;
        *(float2*)(Hout + (size_t)m * 64 + u0) = hn;
    }
}

// ---------------- small kernels ----------------
__global__ void zero_kernel(float* p, size_t n)
{
    size_t i = (size_t)blockIdx.x * blockDim.x + threadIdx.x;
    size_t stride = (size_t)gridDim.x * blockDim.x;
    for (; i < n; i += stride) p[i] = 0.f;
}

__global__ void prep_kernel(const float* __restrict__ Wih_v, const float* __restrict__ Whh_v,
                            const float* __restrict__ bih_v, const float* __restrict__ bhh_v,
                            const float* __restrict__ Wih_s, const float* __restrict__ Whh_s,
                            const float* __restrict__ bih_s, const float* __restrict__ bhh_s,
                            float* __restrict__ S)
{
    int idx = blockIdx.x * blockDim.x + threadIdx.x;
    if (idx < 256 * 128) {
        int o = idx >> 7, k = idx & 127;
        int u = o >> 2, g = o & 3;
        int orow = g * 64 + u;
        S[OFF_WCV + idx] = (k < 64) ? Wih_v[orow * 64 + k] : Whh_v[orow * 64 + (k - 64)];
        S[OFF_WCS + idx] = (k < 64) ? Wih_s[orow * 64 + k] : Whh_s[orow * 64 + (k - 64)];
        if (idx < 256) {
            int uu = idx >> 2, gg = idx & 3;
            int ob = gg * 64 + uu;
            S[OFF_BCV + idx] = bih_v[ob] + bhh_v[ob];
            S[OFF_BCS + idx] = bih_s[ob] + bhh_s[ob];
        }
    }
}

// build W3P / W4P and zero the deg arrays (grid-stride tail)
__global__ void prep2_kernel(const float* __restrict__ W3, const float* __restrict__ W4,
                             float* __restrict__ S)
{
    int idx = blockIdx.x * blockDim.x + threadIdx.x;
    if (idx < 128 * 384) {
        int o = idx / 384, k = idx % 384;
        float v;
        if (k < 128)       v = W4[o * 512 + k];
        else if (k < 256)  v = W4[o * 512 + k] + W4[o * 512 + k + 256];
        else               v = W4[o * 512 + k];
        S[OFF_W4P + o * 384 + k] = v;
    }
    if (idx < 128 * 256) {
        int o = idx >> 8, k = idx & 255;
        float v = (k < 128) ? W3[o * 256 + 128 + k] : W3[o * 256 + (k - 128)];
        S[OFF_W3P + o * 256 + k] = v;
    }
    for (size_t i = idx; i < (size_t)3 * CN; i += (size_t)gridDim.x * blockDim.x)
        S[OFF_DEG + i] = 0.f;
}

// batched gather propagation, grid.y = r
__global__ __launch_bounds__(256) void prop3_kernel(
    const float* __restrict__ pin, int ldin, size_t pin_rstride,
    const int* __restrict__ csrB, const int* __restrict__ offB,
    const float* __restrict__ dinvB, float* __restrict__ outB)
{
    const int r = blockIdx.y;
    const int n = blockIdx.x * 8 + (threadIdx.x >> 5);
    if (n >= CN) return;
    const int lane = threadIdx.x & 31;
    const int col = lane * 4;
    prop_node(n, col, pin + (size_t)r * pin_rstride, ldin,
              csrB + (size_t)r * CE, offB + (size_t)r * (CN + 1),
              dinvB + (size_t)r * CN, outB + (size_t)r * CN * 128);
}

// combine batched over relations: grid.y = r
__global__ __launch_bounds__(256) void attn_comb3_kernel(
    const float* __restrict__ YB,
    const float* __restrict__ BIGp,
    const float* __restrict__ P1B,
    const float* __restrict__ P2B,
    const float* __restrict__ bf1,
    const float* __restrict__ w2,
    float* __restrict__ resB)
{
    const int r = blockIdx.y;
    const int n = blockIdx.x * 8 + (threadIdx.x >> 5);
    if (n >= CN) return;
    const int lane = threadIdx.x & 31;
    const int col = lane * 4;

    const float* Y = YB + (size_t)r * 3 * CN * 128;
    const float* P0 = BIGp + 128 * r;
    const float* P1 = P1B + (size_t)r * CN * 128;
    const float* P2 = P2B + (size_t)r * CN * 128;

    float4 ya = *(const float4*)(Y + (size_t)n * 128 + col);
    float4 yb = *(const float4*)(Y + (size_t)CN * 128 + (size_t)n * 128 + col);
    float4 yc = *(const float4*)(Y + (size_t)2 * CN * 128 + (size_t)n * 128 + col);
    float4 bf = *(const float4*)(bf1 + (size_t)r * 128 + col);
    float4 wl = *(const float4*)(w2 + (size_t)r * 128 + col);

    float sc[5];
#pragma unroll
    for (int f = 0; f < 5; f++) {
        float t0 = c_th0[f], t1 = c_th1[f], t2 = c_th2[f];
        float gx = t0 * ya.x + t1 * yb.x + t2 * yc.x + bf.x;
        float gy = t0 * ya.y + t1 * yb.y + t2 * yc.y + bf.y;
        float gz = t0 * ya.z + t1 * yb.z + t2 * yc.z + bf.z;
        float gw = t0 * ya.w + t1 * yb.w + t2 * yc.w + bf.w;
        float p = tanhf(gx) * wl.x + tanhf(gy) * wl.y + tanhf(gz) * wl.z + tanhf(gw) * wl.w;
#pragma unroll
        for (int off = 16; off; off >>= 1) p += __shfl_xor_sync(0xffffffffu, p, off);
        sc[f] = p;
    }
    float mx = sc[0];
#pragma unroll
    for (int f = 1; f < 5; f++) mx = fmaxf(mx, sc[f]);
    float e[5], s = 0.f;
#pragma unroll
    for (int f = 0; f < 5; f++) { e[f] = expf(sc[f] - mx); s += e[f]; }
    float inv = 1.f / s;
    float ca = 0.f, cb = 0.f, cc = 0.f;
#pragma unroll
    for (int f = 0; f < 5; f++) {
        float w = e[f] * inv;
        ca += w * c_th0[f]; cb += w * c_th1[f]; cc += w * c_th2[f];
    }
    float4 a = *(const float4*)(P0 + (size_t)n * 768 + col);
    float4 b = *(const float4*)(P1 + (size_t)n * 128 + col);
    float4 c = *(const float4*)(P2 + (size_t)n * 128 + col);
    float4 rr = make_float4(ca * a.x + cb * b.x + cc * c.x,
                            ca * a.y + cb * b.y + cc * c.y,
                            ca * a.z + cb * b.z + cc * c.z,
                            ca * a.w + cb * b.w + cc * c.w);
    *(float4*)(resB + (size_t)r * CN * 128 + (size_t)n * 128 + col) = rr;
}

// out[n][c] = b6[c] + sum over 6 partials
__global__ void sumout_kernel(const float* __restrict__ OUTP,
                              const float* __restrict__ b6,
                              float* __restrict__ out)
{
    int n = blockIdx.x * blockDim.x + threadIdx.x;
    if (n >= CN) return;
    float o0 = b6[0], o1 = b6[1];
#pragma unroll
    for (int p = 0; p < 6; p++) {
        o0 += OUTP[(size_t)p * CN * 2 + (size_t)n * 2 + 0];
        o1 += OUTP[(size_t)p * CN * 2 + (size_t)n * 2 + 1];
    }
    out[(size_t)n * 2 + 0] = o0;
    out[(size_t)n * 2 + 1] = o1;
}

// ---------------- orchestration ----------------
extern "C" void kernel_launch(void* const* d_in, const int* in_sizes, int n_in,
                              void* d_out, int out_size)
{
    const float* voc    = (const float*)d_in[0];
    const float* sms    = (const float*)d_in[1];
    const float* pers   = (const float*)d_in[2];
    const float* Wih_v  = (const float*)d_in[3];
    const float* Whh_v  = (const float*)d_in[4];
    const float* bih_v  = (const float*)d_in[5];
    const float* bhh_v  = (const float*)d_in[6];
    const float* Wih_s  = (const float*)d_in[7];
    const float* Whh_s  = (const float*)d_in[8];
    const float* bih_s  = (const float*)d_in[9];
    const float* bhh_s  = (const float*)d_in[10];
    const float* W_lin  = (const float*)d_in[11];
    const float* b_lin  = (const float*)d_in[12];
    const float* W_lin1 = (const float*)d_in[13];
    const float* b_lin1 = (const float*)d_in[14];
    const float* W_pers = (const float*)d_in[15];
    const float* b_pers = (const float*)d_in[16];
    const float* W_lin2 = (const float*)d_in[17];
    const float* b_lin2 = (const float*)d_in[18];
    const float* W_lin3 = (const float*)d_in[19];
    const float* b_lin3 = (const float*)d_in[20];
    const float* W_lin4 = (const float*)d_in[21];
    const float* b_lin4 = (const float*)d_in[22];
    const float* W_lin5 = (const float*)d_in[23];
    const float* b_lin5 = (const float*)d_in[24];
    const float* Wf1    = (const float*)d_in[25];
    const float* bf1    = (const float*)d_in[26];
    const float* Wf2    = (const float*)d_in[27];
    const float* W_lin6 = (const float*)d_in[28];
    const float* b_lin6 = (const float*)d_in[29];
    const int*   src    = (const int*)d_in[30];
    const int*   dst    = (const int*)d_in[31];
    float* out = (float*)d_out;

    float* S = nullptr;
    cudaGetSymbolAddress((void**)&S, g_scratch);
    int* csr = nullptr; cudaGetSymbolAddress((void**)&csr, g_csr);
    int* offp = nullptr; cudaGetSymbolAddress((void**)&offp, g_off);
    int* curp = nullptr; cudaGetSymbolAddress((void**)&curp, g_cur);

    // prep + derived weights (+ deg zero) + zero states
    prep_kernel<<<(256 * 128 + 255) / 256, 256>>>(Wih_v, Whh_v, bih_v, bhh_v,
                                                  Wih_s, Whh_s, bih_s, bhh_s, S);
    prep2_kernel<<<(128 * 384 + 255) / 256, 256>>>(W_lin3, W_lin4, S);
    zero_kernel<<<4096, 256>>>(S + OFF_HV0, (size_t)6 * CN * 64);

    // ---- LSTMs: 16 steps; steps 0-2 piggyback the CSR build (capped aux) ----
    const int ygrid = (CN + 127) / 128;
    for (int t = 0; t < CT; t++) {
        const float* hv_in  = S + ((t & 1) ? OFF_HV1 : OFF_HV0);
        float*       hv_out = S + ((t & 1) ? OFF_HV0 : OFF_HV1);
        const float* hs_in  = S + ((t & 1) ? OFF_HS1 : OFF_HS0);
        float*       hs_out = S + ((t & 1) ? OFF_HS0 : OFF_HS1);
        const int aux = (t == 0) ? 1 : (t == 1) ? 2 : (t == 2) ? 3 : 0;
        dim3 lgrid(aux ? 5 : 4, ygrid);
        lstm_step2_kernel<<<lgrid, 256>>>(voc + (size_t)t * 64, sms + (size_t)t * 64, CT * 64,
                                          hv_in, hs_in,
                                          S + OFF_WCV, S + OFF_WCS,
                                          S + OFF_BCV, S + OFF_BCS,
                                          S + OFF_CV, S + OFF_CS,
                                          hv_out, hs_out,
                                          aux, src, dst,
                                          S + OFF_DEG, offp, curp,
                                          S + OFF_DINV, csr);
    }

    // ---- projections (batched); projB also emits out partials for xin ----
    projA_kernel<<<dim3(3, ygrid), 256>>>(S + OFF_HV0, S + OFF_HS0, pers,
                                          W_lin, b_lin, W_lin1, b_lin1,
                                          W_pers, b_pers, S + OFF_XCAT);
    projB_kernel<<<dim3(3, ygrid), 256>>>(S + OFF_XCAT,
                                          W_lin2, b_lin2,
                                          S + OFF_W3P, b_lin3,
                                          S + OFF_W4P, b_lin4,
                                          W_lin6,
                                          S + OFF_BIG, S + OFF_OUTP);

    // ---- relation graphs (R15-proven structure) ----
    const int pgrid = (CN + 7) / 8;
    const float* BIGp = S + OFF_BIG + 384;

    prop3_kernel<<<dim3(pgrid, 3), 256>>>(BIGp, 768, 128,
                                          csr, offp, S + OFF_DINV, S + OFF_P1);
    prop3_kernel<<<dim3(pgrid, 3), 256>>>(S + OFF_P1, 128, (size_t)CN * 128,
                                          csr, offp, S + OFF_DINV, S + OFF_P2);

    yabc9_kernel<<<dim3(9, ygrid), 256>>>(BIGp, S + OFF_P1, S + OFF_P2,
                                          Wf1, S + OFF_Y);

    attn_comb3_kernel<<<dim3(pgrid, 3), 256>>>(S + OFF_Y, BIGp, S + OFF_P1, S + OFF_P2,
                                               bf1, Wf2, S + OFF_RES);

    // lin5 -> out partials only (hall never materialized)
    lin5o_kernel<<<dim3(3, ygrid), 256>>>(S + OFF_RES, W_lin5, b_lin5,
                                          W_lin6, S + OFF_OUTP);

    // ---- final head: sum 6 partials + bias ----
    sumout_kernel<<<(CN + 255) / 256, 256>>>(S + OFF_OUTP, b_lin6, out);
}